// round 1
// baseline (speedup 1.0000x reference)
#include <cuda_runtime.h>
#include <math.h>

#define Tq 1024
#define Bq 8
#define Dq 1024
#define NH 16
#define DH 64
#define TB (Tq*Bq)       /* 8192 rows */
#define ND (NH*DH)       /* 1024 */
#define N3 (3*ND)        /* 3072 */
#define ZN (Bq*NH)       /* 128 */

// ---- static scratch (zero-initialized at module load; masked region of g_S
//      is never written, so it reads back as prob==0 deterministically) ----
__device__ float g_q[(size_t)ZN*Tq*DH];     // [b][n][t][d]
__device__ float g_k[(size_t)ZN*Tq*DH];
__device__ float g_v[(size_t)ZN*Tq*DH];
__device__ float g_av[(size_t)TB*ND];       // [t*B+b][n*64+d]
__device__ float g_S[(size_t)ZN*Tq*Tq];     // scores -> probs, [z][i][j]

// ============================================================================
// QKV GEMM: C[8192,3072] = (input+pos_enc)[8192,1024] @ W_qkv[1024,3072]
// epilogue scatters into g_q/g_k/g_v with [b][n][t][d] layout.
// 128x128 tile, BK=16, 256 threads, 8x8 micro-tile.
// ============================================================================
__global__ __launch_bounds__(256) void qkv_gemm(const float* __restrict__ inp,
                                                const float* __restrict__ pe,
                                                const float* __restrict__ W) {
    __shared__ float As[16][128];
    __shared__ float Bs[16][132];
    const int tx = threadIdx.x;
    const int m0 = blockIdx.y * 128;
    const int n0 = blockIdx.x * 128;
    const int tr = tx >> 4, tc = tx & 15;
    const int arow = tx >> 2, acol = (tx & 3) << 2;
    const int brow = tx >> 5, bcol = (tx & 31) << 2;

    float acc[8][8];
#pragma unroll
    for (int i = 0; i < 8; i++)
#pragma unroll
        for (int j = 0; j < 8; j++) acc[i][j] = 0.f;

    for (int k0 = 0; k0 < Dq; k0 += 16) {
#pragma unroll
        for (int rr = 0; rr < 2; rr++) {
            int r = arow + rr * 64;
            size_t gi = (size_t)(m0 + r) * Dq + k0 + acol;
            float4 a = *(const float4*)(inp + gi);
            float4 p = *(const float4*)(pe + gi);
            As[acol + 0][r] = a.x + p.x;
            As[acol + 1][r] = a.y + p.y;
            As[acol + 2][r] = a.z + p.z;
            As[acol + 3][r] = a.w + p.w;
        }
#pragma unroll
        for (int rr = 0; rr < 2; rr++) {
            int r = brow + rr * 8;
            float4 b = *(const float4*)(W + (size_t)(k0 + r) * N3 + n0 + bcol);
            *(float4*)&Bs[r][bcol] = b;
        }
        __syncthreads();
#pragma unroll
        for (int kk = 0; kk < 16; kk++) {
            float a[8], b[8];
            *(float4*)&a[0] = *(float4*)&As[kk][tr * 8];
            *(float4*)&a[4] = *(float4*)&As[kk][tr * 8 + 4];
            *(float4*)&b[0] = *(float4*)&Bs[kk][tc * 8];
            *(float4*)&b[4] = *(float4*)&Bs[kk][tc * 8 + 4];
#pragma unroll
            for (int i = 0; i < 8; i++)
#pragma unroll
                for (int j = 0; j < 8; j++) acc[i][j] += a[i] * b[j];
        }
        __syncthreads();
    }

#pragma unroll
    for (int ii = 0; ii < 8; ii++) {
        int row = m0 + tr * 8 + ii;
        int b = row & 7, t = row >> 3;
#pragma unroll
        for (int jj = 0; jj < 8; jj++) {
            int col = n0 + tc * 8 + jj;
            int part = col >> 10;
            int rem = col & 1023;
            int n = rem >> 6, d = rem & 63;
            float* dst = (part == 0) ? g_q : (part == 1) ? g_k : g_v;
            dst[(((b << 4) + n) * Tq + t) * DH + d] = acc[ii][jj];
        }
    }
}

// ============================================================================
// Scores: S[z][i][j] = scale * dot64(Q[z][i], K[z][j]) for j<=i only.
// Triangular tile grid: blockIdx.x enumerates (ti,tj) with tj<=ti. 64x64 tile,
// 256 threads, 4x4 micro-tile, K=64 fully in smem (transposed, padded).
// ============================================================================
__global__ __launch_bounds__(256) void score_kernel() {
    const int z = blockIdx.y;
    const int p = blockIdx.x;
    int ti = 0;
    while ((ti + 1) * (ti + 2) / 2 <= p) ti++;
    const int tj = p - ti * (ti + 1) / 2;

    __shared__ float Qs[DH][68];
    __shared__ float Ks[DH][68];
    const int tx = threadIdx.x;
    const int lrow = tx >> 4, lcol = (tx & 15) << 2;
    const float* qb = g_q + ((size_t)z * Tq + ti * 64) * DH;
    const float* kb = g_k + ((size_t)z * Tq + tj * 64) * DH;
#pragma unroll
    for (int rr = 0; rr < 4; rr++) {
        int r = lrow + rr * 16;
        float4 qv = *(const float4*)(qb + r * DH + lcol);
        Qs[lcol + 0][r] = qv.x; Qs[lcol + 1][r] = qv.y;
        Qs[lcol + 2][r] = qv.z; Qs[lcol + 3][r] = qv.w;
        float4 kv = *(const float4*)(kb + r * DH + lcol);
        Ks[lcol + 0][r] = kv.x; Ks[lcol + 1][r] = kv.y;
        Ks[lcol + 2][r] = kv.z; Ks[lcol + 3][r] = kv.w;
    }
    __syncthreads();

    const int tr = tx >> 4, tc = tx & 15;
    float acc[4][4];
#pragma unroll
    for (int u = 0; u < 4; u++)
#pragma unroll
        for (int v = 0; v < 4; v++) acc[u][v] = 0.f;

#pragma unroll 4
    for (int k = 0; k < 64; k++) {
        float4 a = *(float4*)&Qs[k][tr * 4];
        float4 b = *(float4*)&Ks[k][tc * 4];
        float av[4] = {a.x, a.y, a.z, a.w};
        float bv[4] = {b.x, b.y, b.z, b.w};
#pragma unroll
        for (int u = 0; u < 4; u++)
#pragma unroll
            for (int v = 0; v < 4; v++) acc[u][v] += av[u] * bv[v];
    }

    const float scale = 0.125f;  // 1/sqrt(64)
#pragma unroll
    for (int u = 0; u < 4; u++) {
        int i = ti * 64 + tr * 4 + u;
#pragma unroll
        for (int v = 0; v < 4; v++) {
            int j = tj * 64 + tc * 4 + v;
            if (j <= i) g_S[((size_t)z * Tq + i) * Tq + j] = acc[u][v] * scale;
        }
    }
}

// ============================================================================
// Row softmax in place over j in [0, i]. One 128-thread CTA per row.
// ============================================================================
__global__ __launch_bounds__(128) void softmax_kernel() {
    const int rid = blockIdx.x;          // z*T + i
    const int i = rid & (Tq - 1);
    float* row = g_S + (size_t)rid * Tq;
    const int len = i + 1;
    const int tx = threadIdx.x;

    float vals[8];
    float m = -1e30f;
#pragma unroll
    for (int u = 0; u < 8; u++) {
        int j = tx + u * 128;
        vals[u] = (j < len) ? row[j] : -1e30f;
        m = fmaxf(m, vals[u]);
    }
    __shared__ float redm[4];
    __shared__ float reds[4];
#pragma unroll
    for (int o = 16; o; o >>= 1) m = fmaxf(m, __shfl_xor_sync(0xffffffffu, m, o));
    if ((tx & 31) == 0) redm[tx >> 5] = m;
    __syncthreads();
    m = fmaxf(fmaxf(redm[0], redm[1]), fmaxf(redm[2], redm[3]));

    float s = 0.f;
#pragma unroll
    for (int u = 0; u < 8; u++) {
        int j = tx + u * 128;
        if (j < len) {
            vals[u] = __expf(vals[u] - m);
            s += vals[u];
        }
    }
#pragma unroll
    for (int o = 16; o; o >>= 1) s += __shfl_xor_sync(0xffffffffu, s, o);
    if ((tx & 31) == 0) reds[tx >> 5] = s;
    __syncthreads();
    s = reds[0] + reds[1] + reds[2] + reds[3];

    const float inv = 1.0f / s;
#pragma unroll
    for (int u = 0; u < 8; u++) {
        int j = tx + u * 128;
        if (j < len) row[j] = vals[u] * inv;
    }
}

// ============================================================================
// Coverage: out[b][j][i] = mean_n prob[b][n][i][j]. 32x32 smem-transpose tile.
// Masked region of g_S is zero, so no branches needed except the all-masked
// fast path.
// ============================================================================
__global__ __launch_bounds__(256) void coverage_kernel(float* __restrict__ out_cov) {
    const int b = blockIdx.z;
    const int i0 = blockIdx.y * 32, j0 = blockIdx.x * 32;
    const int tx = threadIdx.x;

    if (j0 >= i0 + 32) {  // fully masked -> zeros, skip the 16 reads
#pragma unroll
        for (int it = 0; it < 4; it++) {
            int idx = tx + it * 256;
            int jj = idx >> 5, ii = idx & 31;
            out_cov[((size_t)b * Tq + j0 + jj) * Tq + i0 + ii] = 0.f;
        }
        return;
    }

    __shared__ float cs[32][33];
#pragma unroll
    for (int it = 0; it < 4; it++) {
        int idx = tx + it * 256;
        int ii = idx >> 5, jj = idx & 31;
        float s = 0.f;
#pragma unroll
        for (int n = 0; n < 16; n++)
            s += g_S[(((size_t)(b * 16 + n) * Tq + i0 + ii) * Tq) + j0 + jj];
        cs[ii][jj] = s * (1.0f / 16.0f);
    }
    __syncthreads();
#pragma unroll
    for (int it = 0; it < 4; it++) {
        int idx = tx + it * 256;
        int jj = idx >> 5, ii = idx & 31;
        out_cov[((size_t)b * Tq + j0 + jj) * Tq + i0 + ii] = cs[ii][jj];
    }
}

// ============================================================================
// PV: attn_vec[i][b][n*64+d] = sum_j prob[z][i][j] * V[z][j][d].
// CTA per (z, i-tile of 64), loops j-tiles 0..ti (causal). 4x4 micro-tile.
// ============================================================================
__global__ __launch_bounds__(256) void av_kernel() {
    const int ti = blockIdx.x;
    const int z = blockIdx.y;
    const int b = z >> 4, n = z & 15;
    __shared__ float Ps[64][68];  // transposed: Ps[j][i]
    __shared__ float Vs[64][68];  // natural:    Vs[j][d]
    const int tx = threadIdx.x;
    const int lrow = tx >> 4, lcol = (tx & 15) << 2;
    const int tr = tx >> 4, tc = tx & 15;

    float acc[4][4];
#pragma unroll
    for (int u = 0; u < 4; u++)
#pragma unroll
        for (int v = 0; v < 4; v++) acc[u][v] = 0.f;

    for (int jt = 0; jt <= ti; jt++) {
        const float* pb = g_S + ((size_t)z * Tq + ti * 64) * Tq + jt * 64;
        const float* vb = g_v + ((size_t)z * Tq + jt * 64) * DH;
#pragma unroll
        for (int rr = 0; rr < 4; rr++) {
            int r = lrow + rr * 16;
            float4 pv = *(const float4*)(pb + (size_t)r * Tq + lcol);
            Ps[lcol + 0][r] = pv.x; Ps[lcol + 1][r] = pv.y;
            Ps[lcol + 2][r] = pv.z; Ps[lcol + 3][r] = pv.w;
            float4 vv = *(const float4*)(vb + r * DH + lcol);
            *(float4*)&Vs[r][lcol] = vv;
        }
        __syncthreads();
#pragma unroll 4
        for (int k = 0; k < 64; k++) {
            float4 a = *(float4*)&Ps[k][tr * 4];
            float4 c = *(float4*)&Vs[k][tc * 4];
            float av[4] = {a.x, a.y, a.z, a.w};
            float cv[4] = {c.x, c.y, c.z, c.w};
#pragma unroll
            for (int u = 0; u < 4; u++)
#pragma unroll
                for (int v = 0; v < 4; v++) acc[u][v] += av[u] * cv[v];
        }
        __syncthreads();
    }

#pragma unroll
    for (int u = 0; u < 4; u++) {
        int i = ti * 64 + tr * 4 + u;
#pragma unroll
        for (int v = 0; v < 4; v++) {
            int d = tc * 4 + v;
            g_av[((size_t)(i * Bq + b)) * ND + n * 64 + d] = acc[u][v];
        }
    }
}

// ============================================================================
// Output projection: out[8192,1024] = g_av[8192,1024] @ W_o[1024,1024]
// ============================================================================
__global__ __launch_bounds__(256) void out_gemm(const float* __restrict__ Wo,
                                                float* __restrict__ out) {
    __shared__ float As[16][128];
    __shared__ float Bs[16][132];
    const int tx = threadIdx.x;
    const int m0 = blockIdx.y * 128;
    const int n0 = blockIdx.x * 128;
    const int tr = tx >> 4, tc = tx & 15;
    const int arow = tx >> 2, acol = (tx & 3) << 2;
    const int brow = tx >> 5, bcol = (tx & 31) << 2;

    float acc[8][8];
#pragma unroll
    for (int i = 0; i < 8; i++)
#pragma unroll
        for (int j = 0; j < 8; j++) acc[i][j] = 0.f;

    for (int k0 = 0; k0 < ND; k0 += 16) {
#pragma unroll
        for (int rr = 0; rr < 2; rr++) {
            int r = arow + rr * 64;
            float4 a = *(const float4*)(g_av + (size_t)(m0 + r) * ND + k0 + acol);
            As[acol + 0][r] = a.x;
            As[acol + 1][r] = a.y;
            As[acol + 2][r] = a.z;
            As[acol + 3][r] = a.w;
        }
#pragma unroll
        for (int rr = 0; rr < 2; rr++) {
            int r = brow + rr * 8;
            float4 b = *(const float4*)(Wo + (size_t)(k0 + r) * ND + n0 + bcol);
            *(float4*)&Bs[r][bcol] = b;
        }
        __syncthreads();
#pragma unroll
        for (int kk = 0; kk < 16; kk++) {
            float a[8], b[8];
            *(float4*)&a[0] = *(float4*)&As[kk][tr * 8];
            *(float4*)&a[4] = *(float4*)&As[kk][tr * 8 + 4];
            *(float4*)&b[0] = *(float4*)&Bs[kk][tc * 8];
            *(float4*)&b[4] = *(float4*)&Bs[kk][tc * 8 + 4];
#pragma unroll
            for (int i = 0; i < 8; i++)
#pragma unroll
                for (int j = 0; j < 8; j++) acc[i][j] += a[i] * b[j];
        }
        __syncthreads();
    }

#pragma unroll
    for (int ii = 0; ii < 8; ii++) {
        int row = m0 + tr * 8 + ii;
#pragma unroll
        for (int jj = 0; jj < 8; jj++) {
            int col = n0 + tc * 8 + jj;
            out[(size_t)row * ND + col] = acc[ii][jj];
        }
    }
}

// ============================================================================
extern "C" void kernel_launch(void* const* d_in, const int* in_sizes, int n_in,
                              void* d_out, int out_size) {
    const float* inp  = (const float*)d_in[0];   // [T,B,D]
    const float* pe   = (const float*)d_in[1];   // [T,B,D]
    // d_in[2] = attn_mask (causal, deterministic) -> unused
    const float* Wqkv = (const float*)d_in[3];   // [D, 3*ND]
    const float* Wo   = (const float*)d_in[4];   // [ND, ND]

    float* out_attn = (float*)d_out;                       // [T,B,ND]
    float* out_cov  = out_attn + (size_t)TB * ND;          // [B,T,T]

    qkv_gemm<<<dim3(N3 / 128, TB / 128), 256>>>(inp, pe, Wqkv);
    score_kernel<<<dim3(136, ZN), 256>>>();
    softmax_kernel<<<ZN * Tq, 128>>>();
    coverage_kernel<<<dim3(Tq / 32, Tq / 32, Bq), 256>>>(out_cov);
    av_kernel<<<dim3(Tq / 64, ZN), 256>>>();
    out_gemm<<<dim3(ND / 128, TB / 128), 256>>>(Wo, out_attn);
}

// round 2
// speedup vs baseline: 2.3497x; 2.3497x over previous
#include <cuda_runtime.h>
#include <stdint.h>
#include <math.h>

#define Tq 1024
#define Bq 8
#define Dq 1024
#define NH 16
#define DH 64
#define TB (Tq*Bq)       /* 8192 rows */
#define ND (NH*DH)       /* 1024 */
#define N3 (3*ND)        /* 3072 */
#define ZN (Bq*NH)       /* 128 */

// ---- static scratch (zero-initialized; masked region of g_S never written) ----
__device__ float g_q[(size_t)ZN*Tq*DH];     // [b][n][t][d]
__device__ float g_k[(size_t)ZN*Tq*DH];
__device__ float g_v[(size_t)ZN*Tq*DH];
__device__ float g_av[(size_t)TB*ND];       // [t*B+b][n*64+d]
__device__ float g_S[(size_t)ZN*Tq*Tq];     // scores -> probs, [z][i][j]

// ---- tf32 helpers ----
__device__ __forceinline__ uint32_t f2tf(float x) {
    uint32_t y;
    asm("cvt.rna.tf32.f32 %0, %1;" : "=r"(y) : "f"(x));
    return y;
}
__device__ __forceinline__ void mma8(float c[4],
                                     uint32_t a0, uint32_t a1, uint32_t a2, uint32_t a3,
                                     uint32_t b0, uint32_t b1) {
    asm volatile("mma.sync.aligned.m16n8k8.row.col.f32.tf32.tf32.f32 "
                 "{%0,%1,%2,%3}, {%4,%5,%6,%7}, {%8,%9}, {%0,%1,%2,%3};\n"
                 : "+f"(c[0]), "+f"(c[1]), "+f"(c[2]), "+f"(c[3])
                 : "r"(a0), "r"(a1), "r"(a2), "r"(a3), "r"(b0), "r"(b1));
}

// ============================================================================
// QKV GEMM (tf32 MMA): C[8192,3072] = (input+pos_enc)[8192,1024] @ W[1024,3072]
// 128x128 CTA tile, BK=32, 8 warps (2x4), warp tile 64x32 (4x4 mma tiles).
// Epilogue scatters into g_q/g_k/g_v [b][n][t][d].
// ============================================================================
__global__ __launch_bounds__(256) void qkv_gemm(const float* __restrict__ inp,
                                                const float* __restrict__ pe,
                                                const float* __restrict__ W) {
    __shared__ __align__(16) uint32_t As[128][36];  // [m][k], stride 36 % 32 == 4
    __shared__ __align__(16) uint32_t Bs[32][136];  // [k][n], stride 136 % 32 == 8
    const int tx = threadIdx.x;
    const int warp = tx >> 5, lane = tx & 31;
    const int g = lane >> 2, tg = lane & 3;
    const int wm = (warp >> 2) * 64;
    const int wn = (warp & 3) * 32;
    const int m0 = blockIdx.y * 128, n0 = blockIdx.x * 128;

    const int la_m = tx >> 3, la_k = (tx & 7) << 2;    // A: 32 rows/pass, 4 passes
    const int lb_k = tx >> 5, lb_n = (tx & 31) << 2;   // B: 8 k-rows/pass, 4 passes

    float acc[4][4][4];
#pragma unroll
    for (int mi = 0; mi < 4; mi++)
#pragma unroll
        for (int ni = 0; ni < 4; ni++)
#pragma unroll
            for (int r = 0; r < 4; r++) acc[mi][ni][r] = 0.f;

    for (int k0 = 0; k0 < Dq; k0 += 32) {
#pragma unroll
        for (int rr = 0; rr < 4; rr++) {
            int m = la_m + rr * 32;
            size_t gi = (size_t)(m0 + m) * Dq + k0 + la_k;
            float4 a = *(const float4*)(inp + gi);
            float4 p = *(const float4*)(pe + gi);
            uint4 v;
            v.x = f2tf(a.x + p.x); v.y = f2tf(a.y + p.y);
            v.z = f2tf(a.z + p.z); v.w = f2tf(a.w + p.w);
            *(uint4*)&As[m][la_k] = v;
        }
#pragma unroll
        for (int rr = 0; rr < 4; rr++) {
            int kk = lb_k + rr * 8;
            float4 b = *(const float4*)(W + (size_t)(k0 + kk) * N3 + n0 + lb_n);
            uint4 v;
            v.x = f2tf(b.x); v.y = f2tf(b.y); v.z = f2tf(b.z); v.w = f2tf(b.w);
            *(uint4*)&Bs[kk][lb_n] = v;
        }
        __syncthreads();
#pragma unroll
        for (int ks = 0; ks < 32; ks += 8) {
            uint32_t a[4][4], b[4][2];
#pragma unroll
            for (int mi = 0; mi < 4; mi++) {
                int r = wm + mi * 16 + g;
                a[mi][0] = As[r][ks + tg];
                a[mi][1] = As[r + 8][ks + tg];
                a[mi][2] = As[r][ks + tg + 4];
                a[mi][3] = As[r + 8][ks + tg + 4];
            }
#pragma unroll
            for (int ni = 0; ni < 4; ni++) {
                int c = wn + ni * 8 + g;
                b[ni][0] = Bs[ks + tg][c];
                b[ni][1] = Bs[ks + tg + 4][c];
            }
#pragma unroll
            for (int mi = 0; mi < 4; mi++)
#pragma unroll
                for (int ni = 0; ni < 4; ni++)
                    mma8(acc[mi][ni], a[mi][0], a[mi][1], a[mi][2], a[mi][3],
                         b[ni][0], b[ni][1]);
        }
        __syncthreads();
    }

#pragma unroll
    for (int mi = 0; mi < 4; mi++)
#pragma unroll
        for (int ni = 0; ni < 4; ni++)
#pragma unroll
            for (int rr = 0; rr < 2; rr++) {
                int row = m0 + wm + mi * 16 + g + rr * 8;
                int b = row & 7, t = row >> 3;
#pragma unroll
                for (int cc = 0; cc < 2; cc++) {
                    int col = n0 + wn + ni * 8 + 2 * tg + cc;
                    int part = col >> 10;
                    int rem = col & 1023;
                    int n = rem >> 6, d = rem & 63;
                    float* dst = (part == 0) ? g_q : (part == 1) ? g_k : g_v;
                    dst[(((size_t)((b << 4) + n) * Tq + t)) * DH + d] = acc[mi][ni][rr * 2 + cc];
                }
            }
}

// ============================================================================
// Scores (tf32 MMA): S[z][i][j] = 0.125*dot64(Q[z][i],K[z][j]), j<=i tiles only.
// 64x64 tile, K=64, 8 warps (2x4), warp tile 32x16 (2x2 mma tiles).
// ============================================================================
__global__ __launch_bounds__(256) void score_kernel() {
    const int z = blockIdx.y;
    const int p = blockIdx.x;
    int ti = 0;
    while ((ti + 1) * (ti + 2) / 2 <= p) ti++;
    const int tj = p - ti * (ti + 1) / 2;

    __shared__ __align__(16) uint32_t Qs[64][68];  // [i][k], 68 % 32 == 4
    __shared__ __align__(16) uint32_t Ks[64][68];  // [j][k]
    const int tx = threadIdx.x;
    const int warp = tx >> 5, lane = tx & 31;
    const int g = lane >> 2, tg = lane & 3;
    const int wm = (warp >> 2) * 32;
    const int wn = (warp & 3) * 16;

    const int lr = tx >> 2, lc0 = (tx & 3) << 2;
    const float* qb = g_q + ((size_t)z * Tq + ti * 64) * DH;
    const float* kb = g_k + ((size_t)z * Tq + tj * 64) * DH;
#pragma unroll
    for (int rr = 0; rr < 4; rr++) {
        int c = lc0 + rr * 16;
        float4 qv = *(const float4*)(qb + lr * DH + c);
        uint4 u;
        u.x = f2tf(qv.x); u.y = f2tf(qv.y); u.z = f2tf(qv.z); u.w = f2tf(qv.w);
        *(uint4*)&Qs[lr][c] = u;
        float4 kv = *(const float4*)(kb + lr * DH + c);
        u.x = f2tf(kv.x); u.y = f2tf(kv.y); u.z = f2tf(kv.z); u.w = f2tf(kv.w);
        *(uint4*)&Ks[lr][c] = u;
    }
    __syncthreads();

    float acc[2][2][4];
#pragma unroll
    for (int mi = 0; mi < 2; mi++)
#pragma unroll
        for (int ni = 0; ni < 2; ni++)
#pragma unroll
            for (int r = 0; r < 4; r++) acc[mi][ni][r] = 0.f;

#pragma unroll
    for (int ks = 0; ks < 64; ks += 8) {
        uint32_t a[2][4], b[2][2];
#pragma unroll
        for (int mi = 0; mi < 2; mi++) {
            int r = wm + mi * 16 + g;
            a[mi][0] = Qs[r][ks + tg];
            a[mi][1] = Qs[r + 8][ks + tg];
            a[mi][2] = Qs[r][ks + tg + 4];
            a[mi][3] = Qs[r + 8][ks + tg + 4];
        }
#pragma unroll
        for (int ni = 0; ni < 2; ni++) {
            int c = wn + ni * 8 + g;
            b[ni][0] = Ks[c][ks + tg];
            b[ni][1] = Ks[c][ks + tg + 4];
        }
#pragma unroll
        for (int mi = 0; mi < 2; mi++)
#pragma unroll
            for (int ni = 0; ni < 2; ni++)
                mma8(acc[mi][ni], a[mi][0], a[mi][1], a[mi][2], a[mi][3],
                     b[ni][0], b[ni][1]);
    }

    const float scale = 0.125f;
#pragma unroll
    for (int mi = 0; mi < 2; mi++)
#pragma unroll
        for (int ni = 0; ni < 2; ni++)
#pragma unroll
            for (int rr = 0; rr < 2; rr++) {
                int i = ti * 64 + wm + mi * 16 + g + rr * 8;
#pragma unroll
                for (int cc = 0; cc < 2; cc++) {
                    int j = tj * 64 + wn + ni * 8 + 2 * tg + cc;
                    if (j <= i)
                        g_S[((size_t)z * Tq + i) * Tq + j] = acc[mi][ni][rr * 2 + cc] * scale;
                }
            }
}

// ============================================================================
// Row softmax in place over j in [0, i]. One 128-thread CTA per row.
// ============================================================================
__global__ __launch_bounds__(128) void softmax_kernel() {
    const int rid = blockIdx.x;
    const int i = rid & (Tq - 1);
    float* row = g_S + (size_t)rid * Tq;
    const int len = i + 1;
    const int tx = threadIdx.x;

    float vals[8];
    float m = -1e30f;
#pragma unroll
    for (int u = 0; u < 8; u++) {
        int j = tx + u * 128;
        vals[u] = (j < len) ? row[j] : -1e30f;
        m = fmaxf(m, vals[u]);
    }
    __shared__ float redm[4];
    __shared__ float reds[4];
#pragma unroll
    for (int o = 16; o; o >>= 1) m = fmaxf(m, __shfl_xor_sync(0xffffffffu, m, o));
    if ((tx & 31) == 0) redm[tx >> 5] = m;
    __syncthreads();
    m = fmaxf(fmaxf(redm[0], redm[1]), fmaxf(redm[2], redm[3]));

    float s = 0.f;
#pragma unroll
    for (int u = 0; u < 8; u++) {
        int j = tx + u * 128;
        if (j < len) {
            vals[u] = __expf(vals[u] - m);
            s += vals[u];
        }
    }
#pragma unroll
    for (int o = 16; o; o >>= 1) s += __shfl_xor_sync(0xffffffffu, s, o);
    if ((tx & 31) == 0) reds[tx >> 5] = s;
    __syncthreads();
    s = reds[0] + reds[1] + reds[2] + reds[3];

    const float inv = 1.0f / s;
#pragma unroll
    for (int u = 0; u < 8; u++) {
        int j = tx + u * 128;
        if (j < len) row[j] = vals[u] * inv;
    }
}

// ============================================================================
// Coverage: out[b][j][i] = mean_n prob[b][n][i][j]. 32x32 smem-transpose tile.
// ============================================================================
__global__ __launch_bounds__(256) void coverage_kernel(float* __restrict__ out_cov) {
    const int b = blockIdx.z;
    const int i0 = blockIdx.y * 32, j0 = blockIdx.x * 32;
    const int tx = threadIdx.x;

    if (j0 >= i0 + 32) {
#pragma unroll
        for (int it = 0; it < 4; it++) {
            int idx = tx + it * 256;
            int jj = idx >> 5, ii = idx & 31;
            out_cov[((size_t)b * Tq + j0 + jj) * Tq + i0 + ii] = 0.f;
        }
        return;
    }

    __shared__ float cs[32][33];
#pragma unroll
    for (int it = 0; it < 4; it++) {
        int idx = tx + it * 256;
        int ii = idx >> 5, jj = idx & 31;
        float s = 0.f;
#pragma unroll
        for (int n = 0; n < 16; n++)
            s += g_S[(((size_t)(b * 16 + n) * Tq + i0 + ii) * Tq) + j0 + jj];
        cs[ii][jj] = s * (1.0f / 16.0f);
    }
    __syncthreads();
#pragma unroll
    for (int it = 0; it < 4; it++) {
        int idx = tx + it * 256;
        int jj = idx >> 5, ii = idx & 31;
        out_cov[((size_t)b * Tq + j0 + jj) * Tq + i0 + ii] = cs[ii][jj];
    }
}

// ============================================================================
// PV (tf32 MMA): attn_vec[i][b][n*64+d] = sum_j prob[z][i][j] * V[z][j][d].
// CTA per (z, i-tile of 64); loops j-stages 0..ti. 8 warps (2x4), 2x2 mma tiles.
// ============================================================================
__global__ __launch_bounds__(256) void av_kernel() {
    const int ti = blockIdx.x;
    const int z = blockIdx.y;
    const int bq = z >> 4, nh = z & 15;
    __shared__ __align__(16) uint32_t Ps[64][68];  // [i][j], 68 % 32 == 4
    __shared__ __align__(16) uint32_t Vs[64][72];  // [j][d], 72 % 32 == 8
    const int tx = threadIdx.x;
    const int warp = tx >> 5, lane = tx & 31;
    const int g = lane >> 2, tg = lane & 3;
    const int wm = (warp >> 2) * 32;
    const int wn = (warp & 3) * 16;
    const int lr = tx >> 2, lc0 = (tx & 3) << 2;

    float acc[2][2][4];
#pragma unroll
    for (int mi = 0; mi < 2; mi++)
#pragma unroll
        for (int ni = 0; ni < 2; ni++)
#pragma unroll
            for (int r = 0; r < 4; r++) acc[mi][ni][r] = 0.f;

    for (int jt = 0; jt <= ti; jt++) {
        const float* pb = g_S + ((size_t)z * Tq + ti * 64) * Tq + jt * 64;
        const float* vb = g_v + ((size_t)z * Tq + jt * 64) * DH;
#pragma unroll
        for (int rr = 0; rr < 4; rr++) {
            int c = lc0 + rr * 16;
            float4 pv = *(const float4*)(pb + (size_t)lr * Tq + c);
            uint4 u;
            u.x = f2tf(pv.x); u.y = f2tf(pv.y); u.z = f2tf(pv.z); u.w = f2tf(pv.w);
            *(uint4*)&Ps[lr][c] = u;
            float4 vv = *(const float4*)(vb + lr * DH + c);
            u.x = f2tf(vv.x); u.y = f2tf(vv.y); u.z = f2tf(vv.z); u.w = f2tf(vv.w);
            *(uint4*)&Vs[lr][c] = u;
        }
        __syncthreads();
#pragma unroll
        for (int ks = 0; ks < 64; ks += 8) {
            uint32_t a[2][4], b[2][2];
#pragma unroll
            for (int mi = 0; mi < 2; mi++) {
                int r = wm + mi * 16 + g;
                a[mi][0] = Ps[r][ks + tg];
                a[mi][1] = Ps[r + 8][ks + tg];
                a[mi][2] = Ps[r][ks + tg + 4];
                a[mi][3] = Ps[r + 8][ks + tg + 4];
            }
#pragma unroll
            for (int ni = 0; ni < 2; ni++) {
                int c = wn + ni * 8 + g;
                b[ni][0] = Vs[ks + tg][c];
                b[ni][1] = Vs[ks + tg + 4][c];
            }
#pragma unroll
            for (int mi = 0; mi < 2; mi++)
#pragma unroll
                for (int ni = 0; ni < 2; ni++)
                    mma8(acc[mi][ni], a[mi][0], a[mi][1], a[mi][2], a[mi][3],
                         b[ni][0], b[ni][1]);
        }
        __syncthreads();
    }

#pragma unroll
    for (int mi = 0; mi < 2; mi++)
#pragma unroll
        for (int ni = 0; ni < 2; ni++)
#pragma unroll
            for (int rr = 0; rr < 2; rr++) {
                int i = ti * 64 + wm + mi * 16 + g + rr * 8;
#pragma unroll
                for (int cc = 0; cc < 2; cc++) {
                    int d = wn + ni * 8 + 2 * tg + cc;
                    g_av[((size_t)(i * Bq + bq)) * ND + nh * 64 + d] = acc[mi][ni][rr * 2 + cc];
                }
            }
}

// ============================================================================
// Output projection (tf32 MMA): out[8192,1024] = g_av @ W_o[1024,1024]
// ============================================================================
__global__ __launch_bounds__(256) void out_gemm(const float* __restrict__ Wo,
                                                float* __restrict__ out) {
    __shared__ __align__(16) uint32_t As[128][36];
    __shared__ __align__(16) uint32_t Bs[32][136];
    const int tx = threadIdx.x;
    const int warp = tx >> 5, lane = tx & 31;
    const int g = lane >> 2, tg = lane & 3;
    const int wm = (warp >> 2) * 64;
    const int wn = (warp & 3) * 32;
    const int m0 = blockIdx.y * 128, n0 = blockIdx.x * 128;

    const int la_m = tx >> 3, la_k = (tx & 7) << 2;
    const int lb_k = tx >> 5, lb_n = (tx & 31) << 2;

    float acc[4][4][4];
#pragma unroll
    for (int mi = 0; mi < 4; mi++)
#pragma unroll
        for (int ni = 0; ni < 4; ni++)
#pragma unroll
            for (int r = 0; r < 4; r++) acc[mi][ni][r] = 0.f;

    for (int k0 = 0; k0 < ND; k0 += 32) {
#pragma unroll
        for (int rr = 0; rr < 4; rr++) {
            int m = la_m + rr * 32;
            float4 a = *(const float4*)(g_av + (size_t)(m0 + m) * ND + k0 + la_k);
            uint4 v;
            v.x = f2tf(a.x); v.y = f2tf(a.y); v.z = f2tf(a.z); v.w = f2tf(a.w);
            *(uint4*)&As[m][la_k] = v;
        }
#pragma unroll
        for (int rr = 0; rr < 4; rr++) {
            int kk = lb_k + rr * 8;
            float4 b = *(const float4*)(Wo + (size_t)(k0 + kk) * ND + n0 + lb_n);
            uint4 v;
            v.x = f2tf(b.x); v.y = f2tf(b.y); v.z = f2tf(b.z); v.w = f2tf(b.w);
            *(uint4*)&Bs[kk][lb_n] = v;
        }
        __syncthreads();
#pragma unroll
        for (int ks = 0; ks < 32; ks += 8) {
            uint32_t a[4][4], b[4][2];
#pragma unroll
            for (int mi = 0; mi < 4; mi++) {
                int r = wm + mi * 16 + g;
                a[mi][0] = As[r][ks + tg];
                a[mi][1] = As[r + 8][ks + tg];
                a[mi][2] = As[r][ks + tg + 4];
                a[mi][3] = As[r + 8][ks + tg + 4];
            }
#pragma unroll
            for (int ni = 0; ni < 4; ni++) {
                int c = wn + ni * 8 + g;
                b[ni][0] = Bs[ks + tg][c];
                b[ni][1] = Bs[ks + tg + 4][c];
            }
#pragma unroll
            for (int mi = 0; mi < 4; mi++)
#pragma unroll
                for (int ni = 0; ni < 4; ni++)
                    mma8(acc[mi][ni], a[mi][0], a[mi][1], a[mi][2], a[mi][3],
                         b[ni][0], b[ni][1]);
        }
        __syncthreads();
    }

#pragma unroll
    for (int mi = 0; mi < 4; mi++)
#pragma unroll
        for (int ni = 0; ni < 4; ni++)
#pragma unroll
            for (int rr = 0; rr < 2; rr++) {
                int row = m0 + wm + mi * 16 + g + rr * 8;
#pragma unroll
                for (int cc = 0; cc < 2; cc++) {
                    int col = n0 + wn + ni * 8 + 2 * tg + cc;
                    out[(size_t)row * ND + col] = acc[mi][ni][rr * 2 + cc];
                }
            }
}

// ============================================================================
extern "C" void kernel_launch(void* const* d_in, const int* in_sizes, int n_in,
                              void* d_out, int out_size) {
    const float* inp  = (const float*)d_in[0];
    const float* pe   = (const float*)d_in[1];
    const float* Wqkv = (const float*)d_in[3];
    const float* Wo   = (const float*)d_in[4];

    float* out_attn = (float*)d_out;
    float* out_cov  = out_attn + (size_t)TB * ND;

    qkv_gemm<<<dim3(N3 / 128, TB / 128), 256>>>(inp, pe, Wqkv);
    score_kernel<<<dim3(136, ZN), 256>>>();
    softmax_kernel<<<ZN * Tq, 128>>>();
    coverage_kernel<<<dim3(Tq / 32, Tq / 32, Bq), 256>>>(out_cov);
    av_kernel<<<dim3(Tq / 64, ZN), 256>>>();
    out_gemm<<<dim3(ND / 128, TB / 128), 256>>>(Wo, out_attn);
}